// round 1
// baseline (speedup 1.0000x reference)
#include <cuda_runtime.h>
#include <math.h>

#define NQ   3
#define FDIM 512
#define NOUT 10
#define PI_F 3.14159265358979323846f

__global__ __launch_bounds__(256)
void quantumnet_fused_kernel(const float* __restrict__ x,       // (B, 512)
                             const float* __restrict__ pre_W,   // (3, 512)
                             const float* __restrict__ pre_b,   // (3,)
                             const float* __restrict__ q_params,// (45,) only [3..8] used
                             const float* __restrict__ post_W,  // (10, 3)
                             const float* __restrict__ post_b,  // (10,)
                             float* __restrict__ out,           // (B, 10)
                             int B) {
    __shared__ float wsh[NQ * FDIM];   // 6 KB

    // Stage pre_W into shared
    for (int i = threadIdx.x; i < NQ * FDIM; i += blockDim.x)
        wsh[i] = pre_W[i];
    __syncthreads();

    const int lane    = threadIdx.x & 31;
    const int warp    = (blockIdx.x * (blockDim.x >> 5)) + (threadIdx.x >> 5);
    const int nwarps  = gridDim.x * (blockDim.x >> 5);

    // Trainable RY layer angles: rows k+1 for k=0,1 -> q_params[3..8]. Hoisted.
    float tc[6], ts[6];
#pragma unroll
    for (int i = 0; i < 6; i++) {
        float th = 0.5f * q_params[3 + i];
        sincosf(th, &ts[i], &tc[i]);
    }
    const float pb0 = pre_b[0], pb1 = pre_b[1], pb2 = pre_b[2];

    const float4* w0p = (const float4*)(wsh);
    const float4* w1p = (const float4*)(wsh + FDIM);
    const float4* w2p = (const float4*)(wsh + 2 * FDIM);

    for (int b = warp; b < B; b += nwarps) {
        const float4* xp = (const float4*)(x + (size_t)b * FDIM);

        float d0 = 0.f, d1 = 0.f, d2 = 0.f;
#pragma unroll
        for (int it = 0; it < 4; it++) {
            int idx = it * 32 + lane;          // 128 float4 per row
            float4 v  = xp[idx];
            float4 a  = w0p[idx];
            float4 bb = w1p[idx];
            float4 c  = w2p[idx];
            d0 += v.x * a.x  + v.y * a.y  + v.z * a.z  + v.w * a.w;
            d1 += v.x * bb.x + v.y * bb.y + v.z * bb.z + v.w * bb.w;
            d2 += v.x * c.x  + v.y * c.y  + v.z * c.z  + v.w * c.w;
        }
        // Butterfly reduce: every lane ends with the full sums
#pragma unroll
        for (int off = 16; off; off >>= 1) {
            d0 += __shfl_xor_sync(0xffffffffu, d0, off);
            d1 += __shfl_xor_sync(0xffffffffu, d1, off);
            d2 += __shfl_xor_sync(0xffffffffu, d2, off);
        }

        // Data encoding angles: theta_j = tanh(pre_out_j) * pi/2; need theta/2
        float h0 = tanhf(d0 + pb0) * (PI_F * 0.25f);
        float h1 = tanhf(d1 + pb1) * (PI_F * 0.25f);
        float h2 = tanhf(d2 + pb2) * (PI_F * 0.25f);

        // --- 3-qubit real state-vector sim (8 amplitudes in registers) ---
        // After H layer on |000>: uniform amplitudes 1/sqrt(8)
        float st[8];
        const float inv8 = 0.3535533905932738f;
#pragma unroll
        for (int i = 0; i < 8; i++) st[i] = inv8;

        // RY(theta) pair update: n0 = c*a0 - s*a1; n1 = s*a0 + c*a1
        // qubit 0 <-> bit 2 (stride 4), qubit 1 <-> bit 1 (stride 2), qubit 2 <-> bit 0 (stride 1)
        float ec, es;
        // encoding RY qubit 0
        sincosf(h0, &es, &ec);
#pragma unroll
        for (int i = 0; i < 4; i++) {
            float a0 = st[i], a1 = st[i + 4];
            st[i]     = ec * a0 - es * a1;
            st[i + 4] = es * a0 + ec * a1;
        }
        // encoding RY qubit 1
        sincosf(h1, &es, &ec);
#pragma unroll
        for (int g = 0; g < 2; g++)
#pragma unroll
            for (int i = 0; i < 2; i++) {
                int i0 = g * 4 + i;
                float a0 = st[i0], a1 = st[i0 + 2];
                st[i0]     = ec * a0 - es * a1;
                st[i0 + 2] = es * a0 + ec * a1;
            }
        // encoding RY qubit 2
        sincosf(h2, &es, &ec);
#pragma unroll
        for (int i0 = 0; i0 < 8; i0 += 2) {
            float a0 = st[i0], a1 = st[i0 + 1];
            st[i0]     = ec * a0 - es * a1;
            st[i0 + 1] = es * a0 + ec * a1;
        }

        // Two entangling+trainable layers
#pragma unroll
        for (int k = 0; k < 2; k++) {
            // CNOT01: control bit2, flip bit1 -> swap (4,6), (5,7)
            float t;
            t = st[4]; st[4] = st[6]; st[6] = t;
            t = st[5]; st[5] = st[7]; st[7] = t;
            // CNOT12: control bit1, flip bit0 -> swap (2,3), (6,7)
            t = st[2]; st[2] = st[3]; st[3] = t;
            t = st[6]; st[6] = st[7]; st[7] = t;

            float c0 = tc[k * 3 + 0], s0 = ts[k * 3 + 0];
            float c1 = tc[k * 3 + 1], s1 = ts[k * 3 + 1];
            float c2 = tc[k * 3 + 2], s2 = ts[k * 3 + 2];
            // RY qubit 0
#pragma unroll
            for (int i = 0; i < 4; i++) {
                float a0 = st[i], a1 = st[i + 4];
                st[i]     = c0 * a0 - s0 * a1;
                st[i + 4] = s0 * a0 + c0 * a1;
            }
            // RY qubit 1
#pragma unroll
            for (int g = 0; g < 2; g++)
#pragma unroll
                for (int i = 0; i < 2; i++) {
                    int i0 = g * 4 + i;
                    float a0 = st[i0], a1 = st[i0 + 2];
                    st[i0]     = c1 * a0 - s1 * a1;
                    st[i0 + 2] = s1 * a0 + c1 * a1;
                }
            // RY qubit 2
#pragma unroll
            for (int i0 = 0; i0 < 8; i0 += 2) {
                float a0 = st[i0], a1 = st[i0 + 1];
                st[i0]     = c2 * a0 - s2 * a1;
                st[i0 + 1] = s2 * a0 + c2 * a1;
            }
        }

        // probs + PauliZ expectations
        float p[8];
#pragma unroll
        for (int i = 0; i < 8; i++) p[i] = st[i] * st[i];
        float z0 = (p[0] + p[1] + p[2] + p[3]) - (p[4] + p[5] + p[6] + p[7]);
        float z1 = (p[0] + p[1] + p[4] + p[5]) - (p[2] + p[3] + p[6] + p[7]);
        float z2 = (p[0] + p[2] + p[4] + p[6]) - (p[1] + p[3] + p[5] + p[7]);

        // Post layer: lanes 0..9 write
        if (lane < NOUT) {
            float o = z0 * post_W[lane * 3 + 0]
                    + z1 * post_W[lane * 3 + 1]
                    + z2 * post_W[lane * 3 + 2]
                    + post_b[lane];
            out[(size_t)b * NOUT + lane] = o;
        }
    }
}

extern "C" void kernel_launch(void* const* d_in, const int* in_sizes, int n_in,
                              void* d_out, int out_size) {
    const float* x       = (const float*)d_in[0];
    const float* pre_W   = (const float*)d_in[1];
    const float* pre_b   = (const float*)d_in[2];
    const float* q_par   = (const float*)d_in[3];
    const float* post_W  = (const float*)d_in[4];
    const float* post_b  = (const float*)d_in[5];
    float* out = (float*)d_out;

    int B = in_sizes[0] / FDIM;

    const int threads = 256;
    int blocks = 1024;                         // grid-stride, ~8 samples/warp
    int warps_needed = (B + 0) ;               // silence unused-warning path
    (void)warps_needed;
    quantumnet_fused_kernel<<<blocks, threads>>>(x, pre_W, pre_b, q_par,
                                                 post_W, post_b, out, B);
}

// round 2
// speedup vs baseline: 1.4547x; 1.4547x over previous
#include <cuda_runtime.h>
#include <math.h>

#define FDIM 512
#define NOUT 10
#define PI_F 3.14159265358979323846f

__device__ __forceinline__ float dot4(float4 a, float4 b) {
    return a.x*b.x + a.y*b.y + a.z*b.z + a.w*b.w;
}

__global__ __launch_bounds__(128)
void quantumnet_v2_kernel(const float* __restrict__ x,        // (B,512)
                          const float* __restrict__ pre_W,    // (3,512)
                          const float* __restrict__ pre_b,    // (3,)
                          const float* __restrict__ q_params, // (45,), rows 1..2 used
                          const float* __restrict__ post_W,   // (10,3)
                          const float* __restrict__ post_b,   // (10,)
                          float* __restrict__ out,            // (B,10)
                          int B)
{
    __shared__ float s_tc[6], s_ts[6], s_pb[3], s_pw[30], s_pbo[10];
    if (threadIdx.x == 0) {
        #pragma unroll
        for (int i = 0; i < 6; i++) {
            float c, s;
            sincosf(0.5f * q_params[3 + i], &s, &c);
            s_ts[i] = s; s_tc[i] = c;
        }
        s_pb[0] = pre_b[0]; s_pb[1] = pre_b[1]; s_pb[2] = pre_b[2];
    }
    if (threadIdx.x < 30) s_pw[threadIdx.x]  = post_W[threadIdx.x];
    if (threadIdx.x < 10) s_pbo[threadIdx.x] = post_b[threadIdx.x];

    const int lane = threadIdx.x & 31;

    // pre_W held in registers: each lane owns columns {it*128+lane*4 .. +3} per row
    float4 wa[4], wb[4], wc[4];
    #pragma unroll
    for (int it = 0; it < 4; it++) {
        wa[it] = ((const float4*)(pre_W          ))[it * 32 + lane];
        wb[it] = ((const float4*)(pre_W +     FDIM))[it * 32 + lane];
        wc[it] = ((const float4*)(pre_W + 2 * FDIM))[it * 32 + lane];
    }
    __syncthreads();

    const int warp = blockIdx.x * (blockDim.x >> 5) + (threadIdx.x >> 5);
    const int base = warp * 32;
    if (base >= B) return;

    // ---------------- Phase A: 32 cooperative dots, transpose to lanes --------
    float md0 = 0.f, md1 = 0.f, md2 = 0.f;   // lane j ends up with sample base+j

    #pragma unroll 2
    for (int j = 0; j < 32; j++) {
        int row = base + j;
        if (row >= B) row = B - 1;
        const float4* xp = (const float4*)(x + (size_t)row * FDIM);
        float4 v0 = xp[lane];
        float4 v1 = xp[32 + lane];
        float4 v2 = xp[64 + lane];
        float4 v3 = xp[96 + lane];

        float d0 = dot4(v0, wa[0]) + dot4(v1, wa[1]) + dot4(v2, wa[2]) + dot4(v3, wa[3]);
        float d1 = dot4(v0, wb[0]) + dot4(v1, wb[1]) + dot4(v2, wb[2]) + dot4(v3, wb[3]);
        float d2 = dot4(v0, wc[0]) + dot4(v1, wc[1]) + dot4(v2, wc[2]) + dot4(v3, wc[3]);

        #pragma unroll
        for (int off = 16; off; off >>= 1) {
            d0 += __shfl_xor_sync(0xffffffffu, d0, off);
            d1 += __shfl_xor_sync(0xffffffffu, d1, off);
            d2 += __shfl_xor_sync(0xffffffffu, d2, off);
        }
        if (lane == j) { md0 = d0; md1 = d1; md2 = d2; }
    }

    // ---------------- Phase B: one sample per lane ----------------------------
    // encoding half-angles: tanh(pre_out)*pi/2, RY uses theta/2 -> *pi/4
    float h0 = tanhf(md0 + s_pb[0]) * (PI_F * 0.25f);
    float h1 = tanhf(md1 + s_pb[1]) * (PI_F * 0.25f);
    float h2 = tanhf(md2 + s_pb[2]) * (PI_F * 0.25f);

    float st[8];
    const float inv8 = 0.3535533905932738f;   // 1/sqrt(8) after H layer on |000>
    #pragma unroll
    for (int i = 0; i < 8; i++) st[i] = inv8;

    float ec, es;
    // encoding RY on qubit 0 (bit2, stride 4)
    sincosf(h0, &es, &ec);
    #pragma unroll
    for (int i = 0; i < 4; i++) {
        float a0 = st[i], a1 = st[i + 4];
        st[i]     = ec * a0 - es * a1;
        st[i + 4] = es * a0 + ec * a1;
    }
    // encoding RY on qubit 1 (bit1, stride 2)
    sincosf(h1, &es, &ec);
    #pragma unroll
    for (int g = 0; g < 2; g++)
        #pragma unroll
        for (int i = 0; i < 2; i++) {
            int i0 = g * 4 + i;
            float a0 = st[i0], a1 = st[i0 + 2];
            st[i0]     = ec * a0 - es * a1;
            st[i0 + 2] = es * a0 + ec * a1;
        }
    // encoding RY on qubit 2 (bit0, stride 1)
    sincosf(h2, &es, &ec);
    #pragma unroll
    for (int i0 = 0; i0 < 8; i0 += 2) {
        float a0 = st[i0], a1 = st[i0 + 1];
        st[i0]     = ec * a0 - es * a1;
        st[i0 + 1] = es * a0 + ec * a1;
    }

    // two entangling + trainable-RY layers
    #pragma unroll
    for (int k = 0; k < 2; k++) {
        float t;
        // CNOT01: swap (4,6),(5,7); CNOT12: swap (2,3),(6,7)
        t = st[4]; st[4] = st[6]; st[6] = t;
        t = st[5]; st[5] = st[7]; st[7] = t;
        t = st[2]; st[2] = st[3]; st[3] = t;
        t = st[6]; st[6] = st[7]; st[7] = t;

        float c0 = s_tc[k * 3 + 0], sg0 = s_ts[k * 3 + 0];
        float c1 = s_tc[k * 3 + 1], sg1 = s_ts[k * 3 + 1];
        float c2 = s_tc[k * 3 + 2], sg2 = s_ts[k * 3 + 2];
        #pragma unroll
        for (int i = 0; i < 4; i++) {
            float a0 = st[i], a1 = st[i + 4];
            st[i]     = c0 * a0 - sg0 * a1;
            st[i + 4] = sg0 * a0 + c0 * a1;
        }
        #pragma unroll
        for (int g = 0; g < 2; g++)
            #pragma unroll
            for (int i = 0; i < 2; i++) {
                int i0 = g * 4 + i;
                float a0 = st[i0], a1 = st[i0 + 2];
                st[i0]     = c1 * a0 - sg1 * a1;
                st[i0 + 2] = sg1 * a0 + c1 * a1;
            }
        #pragma unroll
        for (int i0 = 0; i0 < 8; i0 += 2) {
            float a0 = st[i0], a1 = st[i0 + 1];
            st[i0]     = c2 * a0 - sg2 * a1;
            st[i0 + 1] = sg2 * a0 + c2 * a1;
        }
    }

    float p[8];
    #pragma unroll
    for (int i = 0; i < 8; i++) p[i] = st[i] * st[i];
    float z0 = (p[0] + p[1] + p[2] + p[3]) - (p[4] + p[5] + p[6] + p[7]);
    float z1 = (p[0] + p[1] + p[4] + p[5]) - (p[2] + p[3] + p[6] + p[7]);
    float z2 = (p[0] + p[2] + p[4] + p[6]) - (p[1] + p[3] + p[5] + p[7]);

    // post layer: each lane writes its sample's 10 outputs (union is contiguous)
    int row = base + lane;
    if (row < B) {
        float* op = out + (size_t)row * NOUT;
        #pragma unroll
        for (int k = 0; k < NOUT; k++) {
            op[k] = z0 * s_pw[k * 3 + 0] + z1 * s_pw[k * 3 + 1]
                  + z2 * s_pw[k * 3 + 2] + s_pbo[k];
        }
    }
}

extern "C" void kernel_launch(void* const* d_in, const int* in_sizes, int n_in,
                              void* d_out, int out_size) {
    const float* x      = (const float*)d_in[0];
    const float* pre_W  = (const float*)d_in[1];
    const float* pre_b  = (const float*)d_in[2];
    const float* q_par  = (const float*)d_in[3];
    const float* post_W = (const float*)d_in[4];
    const float* post_b = (const float*)d_in[5];
    float* out = (float*)d_out;

    int B = in_sizes[0] / FDIM;
    int warps_needed  = (B + 31) / 32;
    int blocks        = (warps_needed + 3) / 4;   // 4 warps (128 threads) per block
    quantumnet_v2_kernel<<<blocks, 128>>>(x, pre_W, pre_b, q_par, post_W, post_b, out, B);
}

// round 3
// speedup vs baseline: 1.6483x; 1.1331x over previous
#include <cuda_runtime.h>
#include <math.h>

#define FDIM 512
#define NF4  128          // float4 per row
#define NOUT 10
#define SPW  16           // samples per warp
#define PI_F 3.14159265358979323846f

__device__ __forceinline__ float dot4(float4 a, float4 b) {
    return a.x*b.x + a.y*b.y + a.z*b.z + a.w*b.w;
}

__global__ __launch_bounds__(256)
void quantumnet_v3_kernel(const float* __restrict__ x,        // (B,512)
                          const float* __restrict__ pre_W,    // (3,512)
                          const float* __restrict__ pre_b,    // (3,)
                          const float* __restrict__ q_params, // (45,), rows 1..2 used
                          const float* __restrict__ post_W,   // (10,3)
                          const float* __restrict__ post_b,   // (10,)
                          float* __restrict__ out,            // (B,10)
                          int B)
{
    __shared__ float4 s_w[3 * NF4];                 // 6 KB, pre_W
    __shared__ float  s_tc[6], s_ts[6], s_pb[3], s_pw[30], s_pbo[10];

    for (int i = threadIdx.x; i < 3 * NF4; i += blockDim.x)
        s_w[i] = ((const float4*)pre_W)[i];
    if (threadIdx.x == 0) {
        #pragma unroll
        for (int i = 0; i < 6; i++) {
            float c, s;
            sincosf(0.5f * q_params[3 + i], &s, &c);
            s_ts[i] = s; s_tc[i] = c;
        }
        s_pb[0] = pre_b[0]; s_pb[1] = pre_b[1]; s_pb[2] = pre_b[2];
    }
    if (threadIdx.x < 30) s_pw[threadIdx.x]  = post_W[threadIdx.x];
    if (threadIdx.x < 10) s_pbo[threadIdx.x] = post_b[threadIdx.x];
    __syncthreads();

    const int lane = threadIdx.x & 31;
    const int warp = blockIdx.x * (blockDim.x >> 5) + (threadIdx.x >> 5);
    const int base = warp * SPW;
    if (base >= B) return;

    const int grp = lane >> 3;        // which of 4 concurrent samples
    const int cid = lane & 7;         // column slot within 8-lane group

    float md0 = 0.f, md1 = 0.f, md2 = 0.f;   // lane j (<16) gets sample base+j

    #pragma unroll 1
    for (int i = 0; i < SPW / 4; i++) {
        int s = base + 4 * i + grp;
        if (s >= B) s = B - 1;
        const float4* xp = (const float4*)(x + (size_t)s * FDIM);

        float d0 = 0.f, d1 = 0.f, d2 = 0.f;

        // two half-batches of 8 float4 loads each (MLP=8 per batch)
        #pragma unroll
        for (int h = 0; h < 2; h++) {
            float4 v[8];
            #pragma unroll
            for (int t = 0; t < 8; t++)
                v[t] = xp[cid + h * 64 + 8 * t];
            #pragma unroll
            for (int t = 0; t < 8; t++) {
                int ci = cid + h * 64 + 8 * t;
                d0 += dot4(v[t], s_w[ci]);
                d1 += dot4(v[t], s_w[NF4 + ci]);
                d2 += dot4(v[t], s_w[2 * NF4 + ci]);
            }
        }

        // reduce within each 8-lane group (3 steps)
        #pragma unroll
        for (int off = 4; off; off >>= 1) {
            d0 += __shfl_xor_sync(0xffffffffu, d0, off);
            d1 += __shfl_xor_sync(0xffffffffu, d1, off);
            d2 += __shfl_xor_sync(0xffffffffu, d2, off);
        }
        // gather: lanes 4i..4i+3 capture samples base+4i+0..3 from lanes 0,8,16,24
        int src = (lane & 3) << 3;
        float g0 = __shfl_sync(0xffffffffu, d0, src);
        float g1 = __shfl_sync(0xffffffffu, d1, src);
        float g2 = __shfl_sync(0xffffffffu, d2, src);
        if ((lane >> 2) == i) { md0 = g0; md1 = g1; md2 = g2; }
    }

    // ---------------- Phase B: one sample per lane (lanes 0..15) --------------
    float h0 = tanhf(md0 + s_pb[0]) * (PI_F * 0.25f);
    float h1 = tanhf(md1 + s_pb[1]) * (PI_F * 0.25f);
    float h2 = tanhf(md2 + s_pb[2]) * (PI_F * 0.25f);

    float st[8];
    const float inv8 = 0.3535533905932738f;   // amplitudes after H layer
    #pragma unroll
    for (int i = 0; i < 8; i++) st[i] = inv8;

    float ec, es;
    sincosf(h0, &es, &ec);                    // encoding RY qubit 0 (stride 4)
    #pragma unroll
    for (int i = 0; i < 4; i++) {
        float a0 = st[i], a1 = st[i + 4];
        st[i]     = ec * a0 - es * a1;
        st[i + 4] = es * a0 + ec * a1;
    }
    sincosf(h1, &es, &ec);                    // qubit 1 (stride 2)
    #pragma unroll
    for (int g = 0; g < 2; g++)
        #pragma unroll
        for (int i = 0; i < 2; i++) {
            int i0 = g * 4 + i;
            float a0 = st[i0], a1 = st[i0 + 2];
            st[i0]     = ec * a0 - es * a1;
            st[i0 + 2] = es * a0 + ec * a1;
        }
    sincosf(h2, &es, &ec);                    // qubit 2 (stride 1)
    #pragma unroll
    for (int i0 = 0; i0 < 8; i0 += 2) {
        float a0 = st[i0], a1 = st[i0 + 1];
        st[i0]     = ec * a0 - es * a1;
        st[i0 + 1] = es * a0 + ec * a1;
    }

    #pragma unroll
    for (int k = 0; k < 2; k++) {
        float t;
        // CNOT01: swap (4,6),(5,7); CNOT12: swap (2,3),(6,7)
        t = st[4]; st[4] = st[6]; st[6] = t;
        t = st[5]; st[5] = st[7]; st[7] = t;
        t = st[2]; st[2] = st[3]; st[3] = t;
        t = st[6]; st[6] = st[7]; st[7] = t;

        float c0 = s_tc[k * 3 + 0], sg0 = s_ts[k * 3 + 0];
        float c1 = s_tc[k * 3 + 1], sg1 = s_ts[k * 3 + 1];
        float c2 = s_tc[k * 3 + 2], sg2 = s_ts[k * 3 + 2];
        #pragma unroll
        for (int i = 0; i < 4; i++) {
            float a0 = st[i], a1 = st[i + 4];
            st[i]     = c0 * a0 - sg0 * a1;
            st[i + 4] = sg0 * a0 + c0 * a1;
        }
        #pragma unroll
        for (int g = 0; g < 2; g++)
            #pragma unroll
            for (int i = 0; i < 2; i++) {
                int i0 = g * 4 + i;
                float a0 = st[i0], a1 = st[i0 + 2];
                st[i0]     = c1 * a0 - sg1 * a1;
                st[i0 + 2] = sg1 * a0 + c1 * a1;
            }
        #pragma unroll
        for (int i0 = 0; i0 < 8; i0 += 2) {
            float a0 = st[i0], a1 = st[i0 + 1];
            st[i0]     = c2 * a0 - sg2 * a1;
            st[i0 + 1] = sg2 * a0 + c2 * a1;
        }
    }

    float p[8];
    #pragma unroll
    for (int i = 0; i < 8; i++) p[i] = st[i] * st[i];
    float z0 = (p[0] + p[1] + p[2] + p[3]) - (p[4] + p[5] + p[6] + p[7]);
    float z1 = (p[0] + p[1] + p[4] + p[5]) - (p[2] + p[3] + p[6] + p[7]);
    float z2 = (p[0] + p[2] + p[4] + p[6]) - (p[1] + p[3] + p[5] + p[7]);

    int row = base + lane;
    if (lane < SPW && row < B) {
        float* op = out + (size_t)row * NOUT;
        #pragma unroll
        for (int k = 0; k < NOUT; k++)
            op[k] = z0 * s_pw[k * 3 + 0] + z1 * s_pw[k * 3 + 1]
                  + z2 * s_pw[k * 3 + 2] + s_pbo[k];
    }
}

extern "C" void kernel_launch(void* const* d_in, const int* in_sizes, int n_in,
                              void* d_out, int out_size) {
    const float* x      = (const float*)d_in[0];
    const float* pre_W  = (const float*)d_in[1];
    const float* pre_b  = (const float*)d_in[2];
    const float* q_par  = (const float*)d_in[3];
    const float* post_W = (const float*)d_in[4];
    const float* post_b = (const float*)d_in[5];
    float* out = (float*)d_out;

    int B = in_sizes[0] / FDIM;
    int warps_needed = (B + SPW - 1) / SPW;          // 4096 for B=65536
    int blocks       = (warps_needed + 7) / 8;       // 8 warps / block
    quantumnet_v3_kernel<<<blocks, 256>>>(x, pre_W, pre_b, q_par, post_W, post_b, out, B);
}